// round 9
// baseline (speedup 1.0000x reference)
#include <cuda_runtime.h>
#include <cstdint>

#define N_ROWS 1024
#define X1D 256
#define X2D 128
#define HID 256
#define R 8                 // rows per block
#define NTHR 512
#define NG 8                // k-groups; group h owns k in [h*32, h*32+32)
#define CT 64               // col-threads per group (4 cols each)
#define KPER (HID / NG)     // 32
#define NBLK (N_ROWS / R)   // 128

typedef unsigned long long u64;

__device__ __forceinline__ u64 bcast2(float w) {
    u64 d; asm("mov.b64 %0, {%1, %1};" : "=l"(d) : "f"(w)); return d;
}
__device__ __forceinline__ u64 ffma2(u64 a, u64 b, u64 c) {
    u64 d; asm("fma.rn.f32x2 %0, %1, %2, %3;" : "=l"(d) : "l"(a), "l"(b), "l"(c));
    return d;
}
__device__ __forceinline__ u64 fadd2(u64 a, u64 b) {
    u64 d; asm("add.rn.f32x2 %0, %1, %2;" : "=l"(d) : "l"(a), "l"(b));
    return d;
}
__device__ __forceinline__ void unpack2(float& lo, float& hi, u64 v) {
    asm("mov.b64 {%0, %1}, %2;" : "=f"(lo), "=f"(hi) : "l"(v));
}

// cross-block state (single launch; counters reset by the finisher each run)
__device__ float g_bm[NBLK * X2D];     // per-block column sums of x2
__device__ float g_bs[NBLK * X2D];     // per-block column sums of x2^2
__device__ float g_m[X2D];             // E[x2] per column
__device__ float g_s[X2D];             // E[x2^2] per column
__device__ float g_bout[NBLK];         // per-block scalar partials
__device__ unsigned int g_c1  = 0;     // stats-partials-ready counter
__device__ unsigned int g_c1b = 0;     // stats-combined flag
__device__ unsigned int g_c2  = 0;     // epilogue counter

// ---------------------------------------------------------------------------
// Single fused kernel: stats + 3-layer MLP + CLUB epilogue.
// grid=128 <= SM count, 1 block/SM -> all blocks co-resident, so atomic
// counters + spin are deadlock-free. Mainloop identical to the proven r7
// version: f32x2 packed math, fp32 weights via LDG.128 depth-2 pipeline.
// ---------------------------------------------------------------------------
__global__ void __launch_bounds__(NTHR, 1) club_fused_kernel(
    const float* __restrict__ x1, const float* __restrict__ x2,
    const float* __restrict__ W1, const float* __restrict__ b1,
    const float* __restrict__ W2, const float* __restrict__ b2,
    const float* __restrict__ W3, const float* __restrict__ b3,
    float* __restrict__ out)
{
    extern __shared__ float smem[];
    float* s_part = smem;                      // NG*R*HID = 16384 (64KB)
    float* bufA   = s_part + NG * R * HID;     // 2048
    float* bufB   = bufA + HID * R;            // 2048
    float* s_x2   = bufB + HID * R;            // 1024
    float* s_red  = s_x2 + R * X2D;            // 16

    const int t    = threadIdx.x;
    const int c4   = t & (CT - 1);             // cols 4*c4..4*c4+3
    const int h    = t >> 6;                   // k-group, 0..7
    const int bid  = blockIdx.x;
    const int row0 = bid * R;

    // stage x1 tile transposed: bufA[c*R + r] = x1[row0+r][c]
    {
        int c = t & 255, rr = t >> 8;          // rr in {0,1}
        #pragma unroll
        for (int p = 0; p < 4; p++) {
            int r = rr + p * 2;
            bufA[c * R + r] = x1[(row0 + r) * X1D + c];
        }
    }
    s_x2[t]        = x2[row0 * X2D + t];
    s_x2[t + NTHR] = x2[row0 * X2D + t + NTHR];
    __syncthreads();

    // ---- publish this block's x2 column stats (its own 8 rows) ----
    if (t < X2D) {
        float a = 0.f, q = 0.f;
        #pragma unroll
        for (int r = 0; r < R; r++) {
            float v = s_x2[r * X2D + t];
            a += v;
            q += v * v;
        }
        g_bm[bid * X2D + t] = a;
        g_bs[bid * X2D + t] = q;
    }
    __threadfence();
    __syncthreads();

    __shared__ unsigned int s_comb;
    if (t == 0) {
        unsigned int old = atomicAdd(&g_c1, 1u);
        s_comb = (old == NBLK - 1) ? 1u : 0u;
    }
    __syncthreads();

    // ---- last-arriving block combines stats (overlaps others' MLP work) ----
    if (s_comb) {
        int c = t & 127, g = t >> 7;           // g in 0..3
        float ma = 0.f, mb = 0.f;
        #pragma unroll 4
        for (int b = g; b < NBLK; b += 4) {
            ma += __ldcg(&g_bm[b * X2D + c]);
            mb += __ldcg(&g_bs[b * X2D + c]);
        }
        float* s_cmb = s_part;                 // free until run() below
        s_cmb[g * 128 + c]       = ma;
        s_cmb[512 + g * 128 + c] = mb;
        __syncthreads();
        if (t < X2D) {
            float sm_ = s_cmb[t] + s_cmb[128 + t] + s_cmb[256 + t] + s_cmb[384 + t];
            float ss_ = s_cmb[512 + t] + s_cmb[640 + t] + s_cmb[768 + t] + s_cmb[896 + t];
            g_m[t] = sm_ * (1.0f / N_ROWS);
            g_s[t] = ss_ * (1.0f / N_ROWS);
        }
        __threadfence();
        __syncthreads();
        if (t == 0) atomicExch(&g_c1b, 1u);
    }

    // ---- 3-layer MLP (identical to round-7 mainloop) ----
    auto run = [&](const float* __restrict__ W, const float* __restrict__ B,
                   const float* __restrict__ inb, float* __restrict__ outb,
                   int act) {
        u64 acc[4][4];
        #pragma unroll
        for (int p = 0; p < 4; p++)
            #pragma unroll
            for (int c = 0; c < 4; c++) acc[p][c] = 0ULL;

        const float4* wp =
            reinterpret_cast<const float4*>(W + (h * KPER) * HID) + c4;
        const ulonglong2* ipu =
            reinterpret_cast<const ulonglong2*>(inb + (h * KPER) * R);

        float4 wreg[2];
        wreg[0] = __ldg(wp);
        wreg[1] = __ldg(wp + (HID / 4));

        #pragma unroll
        for (int kk = 0; kk < KPER; kk++) {
            float4 w = wreg[kk & 1];
            if (kk + 2 < KPER)
                wreg[kk & 1] = __ldg(wp + (kk + 2) * (HID / 4));
            u64 wb0 = bcast2(w.x), wb1 = bcast2(w.y);
            u64 wb2 = bcast2(w.z), wb3 = bcast2(w.w);
            ulonglong2 q0 = ipu[2 * kk];
            ulonglong2 q1 = ipu[2 * kk + 1];
            acc[0][0] = ffma2(q0.x, wb0, acc[0][0]);
            acc[0][1] = ffma2(q0.x, wb1, acc[0][1]);
            acc[0][2] = ffma2(q0.x, wb2, acc[0][2]);
            acc[0][3] = ffma2(q0.x, wb3, acc[0][3]);
            acc[1][0] = ffma2(q0.y, wb0, acc[1][0]);
            acc[1][1] = ffma2(q0.y, wb1, acc[1][1]);
            acc[1][2] = ffma2(q0.y, wb2, acc[1][2]);
            acc[1][3] = ffma2(q0.y, wb3, acc[1][3]);
            acc[2][0] = ffma2(q1.x, wb0, acc[2][0]);
            acc[2][1] = ffma2(q1.x, wb1, acc[2][1]);
            acc[2][2] = ffma2(q1.x, wb2, acc[2][2]);
            acc[2][3] = ffma2(q1.x, wb3, acc[2][3]);
            acc[3][0] = ffma2(q1.y, wb0, acc[3][0]);
            acc[3][1] = ffma2(q1.y, wb1, acc[3][1]);
            acc[3][2] = ffma2(q1.y, wb2, acc[3][2]);
            acc[3][3] = ffma2(q1.y, wb3, acc[3][3]);
        }

        {
            ulonglong2* pp = reinterpret_cast<ulonglong2*>(s_part) + h * 512;
            #pragma unroll
            for (int p = 0; p < 4; p++) {
                pp[p * 128 + 2 * c4]     = make_ulonglong2(acc[p][0], acc[p][1]);
                pp[p * 128 + 2 * c4 + 1] = make_ulonglong2(acc[p][2], acc[p][3]);
            }
        }
        __syncthreads();

        {
            const u64* sp = reinterpret_cast<const u64*>(s_part);
            #pragma unroll
            for (int s = 0; s < 2; s++) {
                int slot = t + s * NTHR;
                u64 v = sp[slot];
                #pragma unroll
                for (int gg = 1; gg < NG; gg++)
                    v = fadd2(v, sp[gg * 1024 + slot]);
                int p   = slot >> 8;
                int col = slot & 255;
                float lo, hi;
                unpack2(lo, hi, v);
                float bb = B[col];
                lo += bb; hi += bb;
                if (act) { lo = tanhf(lo); hi = tanhf(hi); }
                else     { lo = fmaxf(lo, 0.f); hi = fmaxf(hi, 0.f); }
                reinterpret_cast<float2*>(outb + col * R + 2 * p)[0] =
                    make_float2(lo, hi);
            }
        }
        __syncthreads();
    };

    run(W1, b1, bufA, bufB, 0);
    run(W2, b2, bufB, bufA, 0);
    run(W3, b3, bufA, bufB, 1);   // g (tanh) in bufB, transposed [col][r]

    // ---- wait for combined stats (normally already done) ----
    if (t == 0) {
        while (atomicAdd(&g_c1b, 0u) == 0u) { __nanosleep(32); }
    }
    __syncthreads();

    // Epilogue: pos-neg = -0.5*iv*( xi^2 - 2*mu*xi + 2*mu*E[x2] - E[x2^2] )
    float part = 0.f;
    #pragma unroll
    for (int s = 0; s < 2; s++) {
        int idx = t + s * NTHR;   // idx = r*128 + d
        int d = idx & 127;
        int r = idx >> 7;
        float mu = bufB[d * R + r];
        float lv = bufB[(X2D + d) * R + r];
        float iv = __expf(-lv);
        float xi = s_x2[r * X2D + d];
        float x2m = __ldcg(&g_m[d]);
        float x2s = __ldcg(&g_s[d]);
        float term = xi * xi - 2.f * mu * xi + 2.f * mu * x2m - x2s;
        part += -0.5f * iv * term;
    }
    #pragma unroll
    for (int off = 16; off > 0; off >>= 1)
        part += __shfl_xor_sync(0xffffffffu, part, off);
    if ((t & 31) == 0) s_red[t >> 5] = part;
    __syncthreads();
    if (t < 16) {
        float v = s_red[t];
        #pragma unroll
        for (int off = 8; off > 0; off >>= 1)
            v += __shfl_xor_sync(0xffffu, v, off);
        if (t == 0) {
            g_bout[bid] = v;
            __threadfence();
            unsigned int old2 = atomicAdd(&g_c2, 1u);
            if (old2 == NBLK - 1) {
                // deterministic fixed-order final reduction
                float s = 0.f;
                #pragma unroll 8
                for (int b = 0; b < NBLK; b++) s += __ldcg(&g_bout[b]);
                out[0] = s * (1.0f / N_ROWS);
                g_c1 = 0u; g_c1b = 0u; g_c2 = 0u;   // reset for next replay
            }
        }
    }
}

// ---------------------------------------------------------------------------

extern "C" void kernel_launch(void* const* d_in, const int* in_sizes, int n_in,
                              void* d_out, int out_size)
{
    const float* x1 = (const float*)d_in[0];
    const float* x2 = (const float*)d_in[1];
    const float* W1 = (const float*)d_in[2];
    const float* b1 = (const float*)d_in[3];
    const float* W2 = (const float*)d_in[4];
    const float* b2 = (const float*)d_in[5];
    const float* W3 = (const float*)d_in[6];
    const float* b3 = (const float*)d_in[7];
    float* out = (float*)d_out;

    const int smem_bytes =
        (NG * R * HID + 2 * HID * R + R * X2D + 16) * sizeof(float);
    static int attr_set = 0;
    if (!attr_set) {
        cudaFuncSetAttribute(club_fused_kernel,
                             cudaFuncAttributeMaxDynamicSharedMemorySize,
                             smem_bytes);
        attr_set = 1;
    }

    club_fused_kernel<<<NBLK, NTHR, smem_bytes>>>(
        x1, x2, W1, b1, W2, b2, W3, b3, out);
}

// round 10
// speedup vs baseline: 1.1892x; 1.1892x over previous
#include <cuda_runtime.h>
#include <cstdint>

#define N_ROWS 1024
#define X1D 256
#define X2D 128
#define HID 256
#define R 8                 // rows per block
#define NTHR 512
#define NG 8                // k-groups; group h owns k in [h*32, h*32+32)
#define CT 64               // col-threads per group (4 cols each)
#define KPER (HID / NG)     // 32
#define NBLK (N_ROWS / R)   // 128

typedef unsigned long long u64;

__device__ __forceinline__ u64 bcast2(float w) {
    u64 d; asm("mov.b64 %0, {%1, %1};" : "=l"(d) : "f"(w)); return d;
}
__device__ __forceinline__ u64 ffma2(u64 a, u64 b, u64 c) {
    u64 d; asm("fma.rn.f32x2 %0, %1, %2, %3;" : "=l"(d) : "l"(a), "l"(b), "l"(c));
    return d;
}
__device__ __forceinline__ u64 fadd2(u64 a, u64 b) {
    u64 d; asm("add.rn.f32x2 %0, %1, %2;" : "=l"(d) : "l"(a), "l"(b));
    return d;
}
__device__ __forceinline__ void unpack2(float& lo, float& hi, u64 v) {
    asm("mov.b64 {%0, %1}, %2;" : "=f"(lo), "=f"(hi) : "l"(v));
}

// cross-block state (single launch; last block resets everything each run)
__device__ float g_m[X2D];             // accumulates E[x2]  (atomicAdd)
__device__ float g_s[X2D];             // accumulates E[x2^2]
__device__ float g_bout[NBLK];         // per-block scalar partials
__device__ unsigned int g_c1 = 0;      // publish counter (target NBLK*X2D)
__device__ unsigned int g_c2 = 0;      // epilogue counter

// ---------------------------------------------------------------------------
// Single fused kernel. grid=128 <= 148 SMs -> all blocks co-resident.
// Stats: fire-and-forget atomicAdd publish in the prologue (no block fence,
// no combiner block); spin check only at the epilogue, long after satisfied.
// Mainloop = round-7 proven code: f32x2 packed math, fp32 weights via
// LDG.128 depth-2 register pipeline, transposed activations in smem.
// ---------------------------------------------------------------------------
__global__ void __launch_bounds__(NTHR, 1) club_fused_kernel(
    const float* __restrict__ x1, const float* __restrict__ x2,
    const float* __restrict__ W1, const float* __restrict__ b1,
    const float* __restrict__ W2, const float* __restrict__ b2,
    const float* __restrict__ W3, const float* __restrict__ b3,
    float* __restrict__ out)
{
    extern __shared__ float smem[];
    float* s_part = smem;                      // NG*R*HID = 16384 (64KB)
    float* bufA   = s_part + NG * R * HID;     // 2048
    float* bufB   = bufA + HID * R;            // 2048
    float* s_x2   = bufB + HID * R;            // 1024
    float* s_red  = s_x2 + R * X2D;            // 16

    const int t    = threadIdx.x;
    const int c4   = t & (CT - 1);             // cols 4*c4..4*c4+3
    const int h    = t >> 6;                   // k-group, 0..7
    const int bid  = blockIdx.x;
    const int row0 = bid * R;

    // stage x1 tile transposed: bufA[c*R + r] = x1[row0+r][c]
    {
        int c = t & 255, rr = t >> 8;          // rr in {0,1}
        #pragma unroll
        for (int p = 0; p < 4; p++) {
            int r = rr + p * 2;
            bufA[c * R + r] = x1[(row0 + r) * X1D + c];
        }
    }
    s_x2[t]        = x2[row0 * X2D + t];
    s_x2[t + NTHR] = x2[row0 * X2D + t + NTHR];
    __syncthreads();

    // ---- fire-and-forget stats publish (128 threads; others fall through) --
    if (t < X2D) {
        float a = 0.f, q = 0.f;
        #pragma unroll
        for (int r = 0; r < R; r++) {
            float v = s_x2[r * X2D + t];
            a += v;
            q += v * v;
        }
        atomicAdd(&g_m[t], a * (1.0f / N_ROWS));
        atomicAdd(&g_s[t], q * (1.0f / N_ROWS));
        __threadfence();                       // per-thread release
        atomicAdd(&g_c1, 1u);
    }
    // NO barrier here — everyone proceeds straight into the mainloop.

    // ---- 3-layer MLP (round-7 mainloop, unchanged) ----
    auto run = [&](const float* __restrict__ W, const float* __restrict__ B,
                   const float* __restrict__ inb, float* __restrict__ outb,
                   int act) {
        u64 acc[4][4];
        #pragma unroll
        for (int p = 0; p < 4; p++)
            #pragma unroll
            for (int c = 0; c < 4; c++) acc[p][c] = 0ULL;

        const float4* wp =
            reinterpret_cast<const float4*>(W + (h * KPER) * HID) + c4;
        const ulonglong2* ipu =
            reinterpret_cast<const ulonglong2*>(inb + (h * KPER) * R);

        float4 wreg[2];
        wreg[0] = __ldg(wp);
        wreg[1] = __ldg(wp + (HID / 4));

        #pragma unroll
        for (int kk = 0; kk < KPER; kk++) {
            float4 w = wreg[kk & 1];
            if (kk + 2 < KPER)
                wreg[kk & 1] = __ldg(wp + (kk + 2) * (HID / 4));
            u64 wb0 = bcast2(w.x), wb1 = bcast2(w.y);
            u64 wb2 = bcast2(w.z), wb3 = bcast2(w.w);
            ulonglong2 q0 = ipu[2 * kk];       // rows (0,1),(2,3)
            ulonglong2 q1 = ipu[2 * kk + 1];   // rows (4,5),(6,7)
            acc[0][0] = ffma2(q0.x, wb0, acc[0][0]);
            acc[0][1] = ffma2(q0.x, wb1, acc[0][1]);
            acc[0][2] = ffma2(q0.x, wb2, acc[0][2]);
            acc[0][3] = ffma2(q0.x, wb3, acc[0][3]);
            acc[1][0] = ffma2(q0.y, wb0, acc[1][0]);
            acc[1][1] = ffma2(q0.y, wb1, acc[1][1]);
            acc[1][2] = ffma2(q0.y, wb2, acc[1][2]);
            acc[1][3] = ffma2(q0.y, wb3, acc[1][3]);
            acc[2][0] = ffma2(q1.x, wb0, acc[2][0]);
            acc[2][1] = ffma2(q1.x, wb1, acc[2][1]);
            acc[2][2] = ffma2(q1.x, wb2, acc[2][2]);
            acc[2][3] = ffma2(q1.x, wb3, acc[2][3]);
            acc[3][0] = ffma2(q1.y, wb0, acc[3][0]);
            acc[3][1] = ffma2(q1.y, wb1, acc[3][1]);
            acc[3][2] = ffma2(q1.y, wb2, acc[3][2]);
            acc[3][3] = ffma2(q1.y, wb3, acc[3][3]);
        }

        {
            ulonglong2* pp = reinterpret_cast<ulonglong2*>(s_part) + h * 512;
            #pragma unroll
            for (int p = 0; p < 4; p++) {
                pp[p * 128 + 2 * c4]     = make_ulonglong2(acc[p][0], acc[p][1]);
                pp[p * 128 + 2 * c4 + 1] = make_ulonglong2(acc[p][2], acc[p][3]);
            }
        }
        __syncthreads();

        {
            const u64* sp = reinterpret_cast<const u64*>(s_part);
            #pragma unroll
            for (int s = 0; s < 2; s++) {
                int slot = t + s * NTHR;
                u64 v = sp[slot];
                #pragma unroll
                for (int gg = 1; gg < NG; gg++)
                    v = fadd2(v, sp[gg * 1024 + slot]);
                int p   = slot >> 8;
                int col = slot & 255;
                float lo, hi;
                unpack2(lo, hi, v);
                float bb = B[col];
                lo += bb; hi += bb;
                if (act) { lo = tanhf(lo); hi = tanhf(hi); }
                else     { lo = fmaxf(lo, 0.f); hi = fmaxf(hi, 0.f); }
                reinterpret_cast<float2*>(outb + col * R + 2 * p)[0] =
                    make_float2(lo, hi);
            }
        }
        __syncthreads();
    };

    run(W1, b1, bufA, bufB, 0);
    run(W2, b2, bufB, bufA, 0);
    run(W3, b3, bufA, bufB, 1);   // g (tanh) in bufB, transposed [col][r]

    // ---- wait for all stat publishes (normally satisfied long ago) ----
    if (t == 0) {
        while (atomicAdd(&g_c1, 0u) < (unsigned)(NBLK * X2D)) __nanosleep(64);
    }
    __syncthreads();

    // Epilogue: pos-neg = -0.5*iv*( xi^2 - 2*mu*xi + 2*mu*E[x2] - E[x2^2] )
    float part = 0.f;
    #pragma unroll
    for (int s = 0; s < 2; s++) {
        int idx = t + s * NTHR;   // idx = r*128 + d
        int d = idx & 127;
        int r = idx >> 7;
        float mu = bufB[d * R + r];
        float lv = bufB[(X2D + d) * R + r];
        float iv = __expf(-lv);
        float xi = s_x2[r * X2D + d];
        float x2m = __ldcg(&g_m[d]);
        float x2s = __ldcg(&g_s[d]);
        float term = xi * xi - 2.f * mu * xi + 2.f * mu * x2m - x2s;
        part += -0.5f * iv * term;
    }
    #pragma unroll
    for (int off = 16; off > 0; off >>= 1)
        part += __shfl_xor_sync(0xffffffffu, part, off);
    if ((t & 31) == 0) s_red[t >> 5] = part;
    __syncthreads();
    if (t == 0) {
        float v = 0.f;
        #pragma unroll
        for (int w = 0; w < NTHR / 32; w++) v += s_red[w];
        __stcg(&g_bout[bid], v);
        __threadfence();
        unsigned int old2 = atomicAdd(&g_c2, 1u);
        if (old2 == NBLK - 1) {
            // deterministic fixed-order final reduction + state reset
            float s = 0.f;
            #pragma unroll 8
            for (int b = 0; b < NBLK; b++) s += __ldcg(&g_bout[b]);
            out[0] = s * (1.0f / N_ROWS);
            #pragma unroll
            for (int d = 0; d < X2D; d++) { g_m[d] = 0.f; g_s[d] = 0.f; }
            g_c1 = 0u;
            g_c2 = 0u;
        }
    }
}

// ---------------------------------------------------------------------------

extern "C" void kernel_launch(void* const* d_in, const int* in_sizes, int n_in,
                              void* d_out, int out_size)
{
    const float* x1 = (const float*)d_in[0];
    const float* x2 = (const float*)d_in[1];
    const float* W1 = (const float*)d_in[2];
    const float* b1 = (const float*)d_in[3];
    const float* W2 = (const float*)d_in[4];
    const float* b2 = (const float*)d_in[5];
    const float* W3 = (const float*)d_in[6];
    const float* b3 = (const float*)d_in[7];
    float* out = (float*)d_out;

    const int smem_bytes =
        (NG * R * HID + 2 * HID * R + R * X2D + 16) * sizeof(float);
    static int attr_set = 0;
    if (!attr_set) {
        cudaFuncSetAttribute(club_fused_kernel,
                             cudaFuncAttributeMaxDynamicSharedMemorySize,
                             smem_bytes);
        attr_set = 1;
    }

    club_fused_kernel<<<NBLK, NTHR, smem_bytes>>>(
        x1, x2, W1, b1, W2, b2, W3, b3, out);
}

// round 11
// speedup vs baseline: 1.4467x; 1.2166x over previous
#include <cuda_runtime.h>
#include <cstdint>

#define N_ROWS 1024
#define X1D 256
#define X2D 128
#define HID 256
#define R 8                 // rows per block
#define NTHR 512
#define NG 8                // k-groups; group h owns k in [h*32, h*32+32)
#define CT 64               // col-threads per group (4 cols each)
#define KPER (HID / NG)     // 32
#define NBLK (N_ROWS / R)   // 128
#define C1_TARGET ((unsigned)(NBLK * X2D))   // 16384

typedef unsigned long long u64;

__device__ __forceinline__ u64 bcast2(float w) {
    u64 d; asm("mov.b64 %0, {%1, %1};" : "=l"(d) : "f"(w)); return d;
}
__device__ __forceinline__ u64 ffma2(u64 a, u64 b, u64 c) {
    u64 d; asm("fma.rn.f32x2 %0, %1, %2, %3;" : "=l"(d) : "l"(a), "l"(b), "l"(c));
    return d;
}
__device__ __forceinline__ u64 fadd2(u64 a, u64 b) {
    u64 d; asm("add.rn.f32x2 %0, %1, %2;" : "=l"(d) : "l"(a), "l"(b));
    return d;
}
__device__ __forceinline__ void unpack2(float& lo, float& hi, u64 v) {
    asm("mov.b64 {%0, %1}, %2;" : "=f"(lo), "=f"(hi) : "l"(v));
}
// gpu-scope reductions/atomics WITHOUT membar (no CCTL.IVALL)
__device__ __forceinline__ void red_add_f32(float* p, float v) {
    asm volatile("red.relaxed.gpu.global.add.f32 [%0], %1;"
                 :: "l"(p), "f"(v) : "memory");
}
__device__ __forceinline__ void red_add_rel_u32(unsigned int* p, unsigned int v) {
    asm volatile("red.release.gpu.global.add.u32 [%0], %1;"
                 :: "l"(p), "r"(v) : "memory");
}
__device__ __forceinline__ unsigned int atom_add_rel_u32(unsigned int* p,
                                                         unsigned int v) {
    unsigned int o;
    asm volatile("atom.release.gpu.global.add.u32 %0, [%1], %2;"
                 : "=r"(o) : "l"(p), "r"(v) : "memory");
    return o;
}
__device__ __forceinline__ unsigned int ld_acq_u32(unsigned int* p) {
    unsigned int o;
    asm volatile("ld.acquire.gpu.global.u32 %0, [%1];"
                 : "=r"(o) : "l"(p) : "memory");
    return o;
}

// cross-block state (single launch; last block resets for graph replays)
__device__ float g_m[X2D];             // accumulates E[x2]   (red.add)
__device__ float g_s[X2D];             // accumulates E[x2^2] (red.add)
__device__ float g_bout[NBLK];         // per-block scalar partials
__device__ unsigned int g_c1 = 0;      // publish counter (target 16384)
__device__ unsigned int g_c2 = 0;      // epilogue counter

// ---------------------------------------------------------------------------
// Single fused kernel. grid=128 <= 148 SMs, 1 block/SM -> co-resident.
// Prologue: fire-and-forget relaxed REDs + release counter (no membar).
// Mainloop: round-7 proven code (f32x2 math, fp32 weights, depth-2 LDG pipe).
// Epilogue: acquire-spin (pre-satisfied), parallel last-block finish.
// ---------------------------------------------------------------------------
__global__ void __launch_bounds__(NTHR, 1) club_fused_kernel(
    const float* __restrict__ x1, const float* __restrict__ x2,
    const float* __restrict__ W1, const float* __restrict__ b1,
    const float* __restrict__ W2, const float* __restrict__ b2,
    const float* __restrict__ W3, const float* __restrict__ b3,
    float* __restrict__ out)
{
    extern __shared__ float smem[];
    float* s_part = smem;                      // NG*R*HID = 16384 (64KB)
    float* bufA   = s_part + NG * R * HID;     // 2048
    float* bufB   = bufA + HID * R;            // 2048
    float* s_x2   = bufB + HID * R;            // 1024
    float* s_red  = s_x2 + R * X2D;            // 16

    __shared__ unsigned int s_lastf;

    const int t    = threadIdx.x;
    const int c4   = t & (CT - 1);             // cols 4*c4..4*c4+3
    const int h    = t >> 6;                   // k-group, 0..7
    const int bid  = blockIdx.x;
    const int row0 = bid * R;

    // stage x1 tile transposed: bufA[c*R + r] = x1[row0+r][c]
    {
        int c = t & 255, rr = t >> 8;          // rr in {0,1}
        #pragma unroll
        for (int p = 0; p < 4; p++) {
            int r = rr + p * 2;
            bufA[c * R + r] = x1[(row0 + r) * X1D + c];
        }
    }
    s_x2[t]        = x2[row0 * X2D + t];
    s_x2[t + NTHR] = x2[row0 * X2D + t + NTHR];
    __syncthreads();

    // ---- fire-and-forget stats publish (128 threads, no fences) ----
    if (t < X2D) {
        float a = 0.f, q = 0.f;
        #pragma unroll
        for (int r = 0; r < R; r++) {
            float v = s_x2[r * X2D + t];
            a += v;
            q += v * v;
        }
        red_add_f32(&g_m[t], a * (1.0f / N_ROWS));
        red_add_f32(&g_s[t], q * (1.0f / N_ROWS));
        red_add_rel_u32(&g_c1, 1u);            // release orders the two REDs
    }
    // no barrier — straight into the mainloop

    // ---- 3-layer MLP (round-7 mainloop, unchanged) ----
    auto run = [&](const float* __restrict__ W, const float* __restrict__ B,
                   const float* __restrict__ inb, float* __restrict__ outb,
                   int act) {
        u64 acc[4][4];
        #pragma unroll
        for (int p = 0; p < 4; p++)
            #pragma unroll
            for (int c = 0; c < 4; c++) acc[p][c] = 0ULL;

        const float4* wp =
            reinterpret_cast<const float4*>(W + (h * KPER) * HID) + c4;
        const ulonglong2* ipu =
            reinterpret_cast<const ulonglong2*>(inb + (h * KPER) * R);

        float4 wreg[2];
        wreg[0] = __ldg(wp);
        wreg[1] = __ldg(wp + (HID / 4));

        #pragma unroll
        for (int kk = 0; kk < KPER; kk++) {
            float4 w = wreg[kk & 1];
            if (kk + 2 < KPER)
                wreg[kk & 1] = __ldg(wp + (kk + 2) * (HID / 4));
            u64 wb0 = bcast2(w.x), wb1 = bcast2(w.y);
            u64 wb2 = bcast2(w.z), wb3 = bcast2(w.w);
            ulonglong2 q0 = ipu[2 * kk];       // rows (0,1),(2,3)
            ulonglong2 q1 = ipu[2 * kk + 1];   // rows (4,5),(6,7)
            acc[0][0] = ffma2(q0.x, wb0, acc[0][0]);
            acc[0][1] = ffma2(q0.x, wb1, acc[0][1]);
            acc[0][2] = ffma2(q0.x, wb2, acc[0][2]);
            acc[0][3] = ffma2(q0.x, wb3, acc[0][3]);
            acc[1][0] = ffma2(q0.y, wb0, acc[1][0]);
            acc[1][1] = ffma2(q0.y, wb1, acc[1][1]);
            acc[1][2] = ffma2(q0.y, wb2, acc[1][2]);
            acc[1][3] = ffma2(q0.y, wb3, acc[1][3]);
            acc[2][0] = ffma2(q1.x, wb0, acc[2][0]);
            acc[2][1] = ffma2(q1.x, wb1, acc[2][1]);
            acc[2][2] = ffma2(q1.x, wb2, acc[2][2]);
            acc[2][3] = ffma2(q1.x, wb3, acc[2][3]);
            acc[3][0] = ffma2(q1.y, wb0, acc[3][0]);
            acc[3][1] = ffma2(q1.y, wb1, acc[3][1]);
            acc[3][2] = ffma2(q1.y, wb2, acc[3][2]);
            acc[3][3] = ffma2(q1.y, wb3, acc[3][3]);
        }

        {
            ulonglong2* pp = reinterpret_cast<ulonglong2*>(s_part) + h * 512;
            #pragma unroll
            for (int p = 0; p < 4; p++) {
                pp[p * 128 + 2 * c4]     = make_ulonglong2(acc[p][0], acc[p][1]);
                pp[p * 128 + 2 * c4 + 1] = make_ulonglong2(acc[p][2], acc[p][3]);
            }
        }
        __syncthreads();

        {
            const u64* sp = reinterpret_cast<const u64*>(s_part);
            #pragma unroll
            for (int s = 0; s < 2; s++) {
                int slot = t + s * NTHR;
                u64 v = sp[slot];
                #pragma unroll
                for (int gg = 1; gg < NG; gg++)
                    v = fadd2(v, sp[gg * 1024 + slot]);
                int p   = slot >> 8;
                int col = slot & 255;
                float lo, hi;
                unpack2(lo, hi, v);
                float bb = B[col];
                lo += bb; hi += bb;
                if (act) { lo = tanhf(lo); hi = tanhf(hi); }
                else     { lo = fmaxf(lo, 0.f); hi = fmaxf(hi, 0.f); }
                reinterpret_cast<float2*>(outb + col * R + 2 * p)[0] =
                    make_float2(lo, hi);
            }
        }
        __syncthreads();
    };

    run(W1, b1, bufA, bufB, 0);
    run(W2, b2, bufB, bufA, 0);
    run(W3, b3, bufA, bufB, 1);   // g (tanh) in bufB, transposed [col][r]

    // ---- wait for all stat publishes (normally satisfied long ago) ----
    if (t == 0) {
        while (ld_acq_u32(&g_c1) < C1_TARGET) __nanosleep(64);
    }
    __syncthreads();

    // Epilogue: pos-neg = -0.5*iv*( xi^2 - 2*mu*xi + 2*mu*E[x2] - E[x2^2] )
    float part = 0.f;
    #pragma unroll
    for (int s = 0; s < 2; s++) {
        int idx = t + s * NTHR;   // idx = r*128 + d
        int d = idx & 127;
        int r = idx >> 7;
        float mu = bufB[d * R + r];
        float lv = bufB[(X2D + d) * R + r];
        float iv = __expf(-lv);
        float xi = s_x2[r * X2D + d];
        float x2m = __ldcg(&g_m[d]);
        float x2s = __ldcg(&g_s[d]);
        float term = xi * xi - 2.f * mu * xi + 2.f * mu * x2m - x2s;
        part += -0.5f * iv * term;
    }
    #pragma unroll
    for (int off = 16; off > 0; off >>= 1)
        part += __shfl_xor_sync(0xffffffffu, part, off);
    if ((t & 31) == 0) s_red[t >> 5] = part;
    __syncthreads();
    if (t < 16) {
        float v = s_red[t];
        #pragma unroll
        for (int off = 8; off > 0; off >>= 1)
            v += __shfl_xor_sync(0xffffu, v, off);
        if (t == 0) {
            __stcg(&g_bout[bid], v);
            unsigned int old2 = atom_add_rel_u32(&g_c2, 1u);  // orders stcg
            s_lastf = (old2 == NBLK - 1) ? 1u : 0u;
        }
    }
    __syncthreads();

    // ---- elected last block: parallel final reduction + state reset ----
    if (s_lastf) {
        float bv = 0.f;
        if (t < NBLK) bv = __ldcg(&g_bout[t]);   // one coalesced wavefront
        if (t < NBLK) {
            #pragma unroll
            for (int off = 16; off > 0; off >>= 1)
                bv += __shfl_xor_sync(0xffffffffu, bv, off);
            if ((t & 31) == 0) s_red[t >> 5] = bv;   // 4 warp sums
        }
        // parallel state reset for the next graph replay
        if (t >= 128 && t < 256) {
            __stcg(&g_m[t - 128], 0.f);
            __stcg(&g_s[t - 128], 0.f);
        }
        __syncthreads();
        if (t == 0) {
            float s = s_red[0] + s_red[1] + s_red[2] + s_red[3];
            out[0] = s * (1.0f / N_ROWS);
            g_c1 = 0u;
            g_c2 = 0u;
        }
    }
}

// ---------------------------------------------------------------------------

extern "C" void kernel_launch(void* const* d_in, const int* in_sizes, int n_in,
                              void* d_out, int out_size)
{
    const float* x1 = (const float*)d_in[0];
    const float* x2 = (const float*)d_in[1];
    const float* W1 = (const float*)d_in[2];
    const float* b1 = (const float*)d_in[3];
    const float* W2 = (const float*)d_in[4];
    const float* b2 = (const float*)d_in[5];
    const float* W3 = (const float*)d_in[6];
    const float* b3 = (const float*)d_in[7];
    float* out = (float*)d_out;

    const int smem_bytes =
        (NG * R * HID + 2 * HID * R + R * X2D + 16) * sizeof(float);
    static int attr_set = 0;
    if (!attr_set) {
        cudaFuncSetAttribute(club_fused_kernel,
                             cudaFuncAttributeMaxDynamicSharedMemorySize,
                             smem_bytes);
        attr_set = 1;
    }

    club_fused_kernel<<<NBLK, NTHR, smem_bytes>>>(
        x1, x2, W1, b1, W2, b2, W3, b3, out);
}